// round 3
// baseline (speedup 1.0000x reference)
#include <cuda_runtime.h>
#include <cuda_fp16.h>

#define N_NODES 50000
#define N_EDGES 800000
#define DD 128
#define NEG 0.2f
#define NLAB 8
#define ET (N_EDGES + N_NODES)
#define WSZ (7 * DD * DD)

// ---------------- device scratch (no allocs allowed) ----------------
__device__ __align__(16) uint2 g_oxh[N_NODES * 32];  // fp16x4 packed transformed features
__device__ __align__(16) __half g_Wh[WSZ];           // fp16 weights
__device__ float g_ai[N_NODES];
__device__ float g_aj[N_NODES];
__device__ unsigned g_ajmax_u;                       // ordered-uint encoded max(aj)
__device__ int   g_order[N_NODES];
__device__ int   g_counts[NLAB];
__device__ int   g_base[NLAB + 1];
__device__ int   g_lcur[NLAB];
__device__ int   g_deg[N_NODES];
__device__ int   g_off[N_NODES + 1];
__device__ int   g_cur[N_NODES];
__device__ int   g_csr[ET];

__device__ __forceinline__ unsigned fenc(float f) {
    unsigned u = __float_as_uint(f);
    return (u & 0x80000000u) ? ~u : (u | 0x80000000u);
}
__device__ __forceinline__ float fdec(unsigned u) {
    return (u & 0x80000000u) ? __uint_as_float(u ^ 0x80000000u)
                             : __uint_as_float(~u);
}
__device__ __forceinline__ float lrelu(float a) { return a > 0.f ? a : NEG * a; }

// ---------------- init: counters, degrees, W->fp16 ----------------
__global__ void k_init(const float* __restrict__ W) {
    int i = blockIdx.x * blockDim.x + threadIdx.x;
    if (i < NLAB) g_counts[i] = 0;
    if (i == NLAB) g_ajmax_u = 0u;   // encodes -inf
    if (i < N_NODES) g_deg[i] = 1;   // self loop pre-counted
    if (i < WSZ) g_Wh[i] = __float2half_rn(W[i]);
}

// label histogram (warp-aggregated) + in-degree count
__global__ void k_count(const int* __restrict__ ei, const int* __restrict__ label) {
    int i = blockIdx.x * blockDim.x + threadIdx.x;
    if (i < N_NODES) {
        int lb = label[i];
        if (lb < 1 || lb > 7) lb = 0;
        unsigned act = __activemask();
        unsigned peers = __match_any_sync(act, lb);
        int leader = __ffs(peers) - 1;
        if ((int)(threadIdx.x & 31) == leader)
            atomicAdd(&g_counts[lb], __popc(peers));
    }
    if (i < N_EDGES) {
        atomicAdd(&g_deg[ei[N_EDGES + i]], 1);  // dst
    }
}

// single block: label bases + exclusive scan of degrees
__global__ void k_scan() {
    __shared__ int ssum[1024];
    int t = threadIdx.x;
    if (t == 0) {
        int b = 0;
        for (int k = 0; k < NLAB; k++) { g_base[k] = b; g_lcur[k] = b; b += g_counts[k]; }
        g_base[NLAB] = b;
    }
    const int CH = (N_NODES + 1023) / 1024;  // 49
    int b0 = t * CH;
    int s = 0;
    for (int i = 0; i < CH; i++) {
        int idx = b0 + i;
        if (idx < N_NODES) s += g_deg[idx];
    }
    ssum[t] = s;
    __syncthreads();
    for (int off = 1; off < 1024; off <<= 1) {
        int v = (t >= off) ? ssum[t - off] : 0;
        __syncthreads();
        ssum[t] += v;
        __syncthreads();
    }
    int run = (t == 0) ? 0 : ssum[t - 1];
    for (int i = 0; i < CH; i++) {
        int idx = b0 + i;
        if (idx < N_NODES) {
            g_off[idx] = run;
            g_cur[idx] = run;
            run += g_deg[idx];
        }
    }
    if (t == 1023) g_off[N_NODES] = ssum[1023];
}

// fused: label-group scatter (i < N) + CSR fill (i < ET)
__global__ void k_build(const int* __restrict__ ei, const int* __restrict__ label) {
    int i = blockIdx.x * blockDim.x + threadIdx.x;
    if (i < N_NODES) {
        int lb = label[i];
        if (lb < 1 || lb > 7) lb = 0;
        unsigned act = __activemask();
        unsigned peers = __match_any_sync(act, lb);
        int leader = __ffs(peers) - 1;
        int lane = threadIdx.x & 31;
        int rank = __popc(peers & ((1u << lane) - 1u));
        int basePos = 0;
        if (lane == leader) basePos = atomicAdd(&g_lcur[lb], __popc(peers));
        basePos = __shfl_sync(act, basePos, leader);
        g_order[basePos + rank] = i;
    }
    if (i < N_EDGES) {
        int s = ei[i];
        int d = ei[N_EDGES + i];
        int pos = atomicAdd(&g_cur[d], 1);
        g_csr[pos] = s;
    } else if (i < ET) {
        int n = i - N_EDGES;
        int pos = atomicAdd(&g_cur[n], 1);
        g_csr[pos] = n;
    }
}

// tensor-core label-grouped GEMM: ox = x + W[k-1]^T x (64 nodes x 128 out / block)
// + fused epilogue: fp16 pack, ai/aj attention dots, global aj max
__global__ void __launch_bounds__(128) k_ox(const float* __restrict__ x,
                                            const float* __restrict__ att) {
    int k = blockIdx.y;
    int gbase = g_base[k];
    int start = gbase + blockIdx.x * 64;
    int end   = gbase + g_counts[k];
    if (start >= end) return;
    int nEff = min(64, end - start);

    __shared__ __align__(16) __half xs[64 * DD];   // 16KB: node tile, fp16
    __shared__ __align__(16) __half ws[64 * DD];   // 16KB: W k-chunk / ox staging
    __shared__ int nid[64];

    int tid = threadIdx.x;
    int lane = tid & 31, wid = tid >> 5;
    if (tid < 64) nid[tid] = (tid < nEff) ? g_order[start + tid] : g_order[start];
    __syncthreads();

    // stage x rows (fp32 -> fp16, coalesced halves-of-row per thread)
    {
        int j = tid >> 1, part = tid & 1;
        const float4* xr = (const float4*)x + (size_t)nid[j] * 32 + part * 16;
        __half2* dst = (__half2*)(xs + j * DD + part * 64);
#pragma unroll
        for (int i = 0; i < 16; i++) {
            float4 v = xr[i];
            dst[i * 2 + 0] = __floats2half2_rn(v.x, v.y);
            dst[i * 2 + 1] = __floats2half2_rn(v.z, v.w);
        }
    }

    float d[16][4];
#pragma unroll
    for (int nt = 0; nt < 16; nt++) { d[nt][0] = d[nt][1] = d[nt][2] = d[nt][3] = 0.f; }

    int wrow0 = wid * 16;  // warp's 16-row strip

    if (k > 0) {
        const int4* Wg = (const int4*)(g_Wh + (size_t)(k - 1) * DD * DD);
        for (int c = 0; c < 2; c++) {   // two 64-deep K chunks
            __syncthreads();
            {
                int4* wd = (int4*)ws;
                const int4* wsrc = Wg + c * 1024;
                for (int i = tid; i < 1024; i += 128) wd[i] = wsrc[i];
            }
            __syncthreads();
#pragma unroll
            for (int kt = 0; kt < 4; kt++) {
                int kb = kt * 16;
                // A fragment (m16k16) via ldmatrix.x4
                unsigned a0, a1, a2, a3;
                {
                    int r  = (lane & 7) + ((lane >> 3) & 1) * 8;
                    int cc = (lane >> 4) * 8;
                    const __half* ap = xs + (wrow0 + r) * DD + (c * 64 + kb + cc);
                    unsigned sa = (unsigned)__cvta_generic_to_shared(ap);
                    asm volatile("ldmatrix.sync.aligned.m8n8.x4.shared.b16 {%0,%1,%2,%3}, [%4];"
                                 : "=r"(a0), "=r"(a1), "=r"(a2), "=r"(a3) : "r"(sa));
                }
#pragma unroll
                for (int np = 0; np < 8; np++) {  // pairs of n8 tiles
                    int n0 = np * 16;
                    unsigned b0, b1, b2, b3;
                    {
                        int kr = kb + (lane & 7) + ((lane >> 3) & 1) * 8;
                        int nc = n0 + (lane >> 4) * 8;
                        const __half* bp = ws + kr * DD + nc;
                        unsigned sb = (unsigned)__cvta_generic_to_shared(bp);
                        asm volatile("ldmatrix.sync.aligned.m8n8.x4.trans.shared.b16 {%0,%1,%2,%3}, [%4];"
                                     : "=r"(b0), "=r"(b1), "=r"(b2), "=r"(b3) : "r"(sb));
                    }
                    asm volatile("mma.sync.aligned.m16n8k16.row.col.f32.f16.f16.f32 "
                                 "{%0,%1,%2,%3}, {%4,%5,%6,%7}, {%8,%9}, {%0,%1,%2,%3};"
                                 : "+f"(d[np*2][0]), "+f"(d[np*2][1]), "+f"(d[np*2][2]), "+f"(d[np*2][3])
                                 : "r"(a0), "r"(a1), "r"(a2), "r"(a3), "r"(b0), "r"(b1));
                    asm volatile("mma.sync.aligned.m16n8k16.row.col.f32.f16.f16.f32 "
                                 "{%0,%1,%2,%3}, {%4,%5,%6,%7}, {%8,%9}, {%0,%1,%2,%3};"
                                 : "+f"(d[np*2+1][0]), "+f"(d[np*2+1][1]), "+f"(d[np*2+1][2]), "+f"(d[np*2+1][3])
                                 : "r"(a0), "r"(a1), "r"(a2), "r"(a3), "r"(b2), "r"(b3));
                }
            }
        }
    }
    __syncthreads();   // done with ws as W; reuse as ox staging

    __half* os = ws;
    {
        int r0 = wrow0 + (lane >> 2);
        int r1 = r0 + 8;
#pragma unroll
        for (int nt = 0; nt < 16; nt++) {
            int cc = nt * 8 + 2 * (lane & 3);
            float x00 = __half2float(xs[r0 * DD + cc]);
            float x01 = __half2float(xs[r0 * DD + cc + 1]);
            float x10 = __half2float(xs[r1 * DD + cc]);
            float x11 = __half2float(xs[r1 * DD + cc + 1]);
            *(__half2*)(os + r0 * DD + cc) = __floats2half2_rn(x00 + d[nt][0], x01 + d[nt][1]);
            *(__half2*)(os + r1 * DD + cc) = __floats2half2_rn(x10 + d[nt][2], x11 + d[nt][3]);
        }
    }
    __syncthreads();

    // attention dots + pack-out (warp w owns rows wrow0..wrow0+15)
    float4 af = ((const float4*)att)[lane];
    float4 bf = ((const float4*)att)[32 + lane];
    for (int t = 0; t < 16; t++) {
        int j = wrow0 + t;
        uint2 p = ((const uint2*)os)[j * 32 + lane];
        float2 f01 = __half22float2(*reinterpret_cast<const __half2*>(&p.x));
        float2 f23 = __half22float2(*reinterpret_cast<const __half2*>(&p.y));
        float si = f01.x * af.x + f01.y * af.y + f23.x * af.z + f23.y * af.w;
        float sj = f01.x * bf.x + f01.y * bf.y + f23.x * bf.z + f23.y * bf.w;
#pragma unroll
        for (int o = 16; o; o >>= 1) {
            si += __shfl_xor_sync(0xFFFFFFFFu, si, o);
            sj += __shfl_xor_sync(0xFFFFFFFFu, sj, o);
        }
        if (j < nEff) {
            int node = nid[j];
            g_oxh[node * 32 + lane] = p;
            if (lane == 0) {
                g_ai[node] = si;
                g_aj[node] = sj;
                atomicMax(&g_ajmax_u, fenc(sj));
            }
        }
    }
}

// warp per dst node: single-pass softmax (global aj-max bound) + fp16 gather
__global__ void __launch_bounds__(256) k_agg(float* __restrict__ out) {
    int node = (blockIdx.x * blockDim.x + threadIdx.x) >> 5;
    int lane = threadIdx.x & 31;
    if (node >= N_NODES) return;
    int beg = g_off[node], end2 = g_off[node + 1];
    float ain = g_ai[node];
    float Mi = lrelu(ain + fdec(g_ajmax_u));  // upper bound on all alphas of this node

    float4 acc = make_float4(0.f, 0.f, 0.f, 0.f);
    float denom = 0.f;
    int e = beg;
    for (; e + 4 <= end2; e += 4) {
        int s0 = g_csr[e], s1 = g_csr[e + 1], s2 = g_csr[e + 2], s3 = g_csr[e + 3];
        float w0 = __expf(lrelu(ain + g_aj[s0]) - Mi);
        float w1 = __expf(lrelu(ain + g_aj[s1]) - Mi);
        float w2 = __expf(lrelu(ain + g_aj[s2]) - Mi);
        float w3 = __expf(lrelu(ain + g_aj[s3]) - Mi);
        uint2 p0 = g_oxh[s0 * 32 + lane];
        uint2 p1 = g_oxh[s1 * 32 + lane];
        uint2 p2 = g_oxh[s2 * 32 + lane];
        uint2 p3 = g_oxh[s3 * 32 + lane];
        denom += (w0 + w1) + (w2 + w3);
        float2 f01, f23;
        f01 = __half22float2(*reinterpret_cast<const __half2*>(&p0.x));
        f23 = __half22float2(*reinterpret_cast<const __half2*>(&p0.y));
        acc.x += w0 * f01.x; acc.y += w0 * f01.y; acc.z += w0 * f23.x; acc.w += w0 * f23.y;
        f01 = __half22float2(*reinterpret_cast<const __half2*>(&p1.x));
        f23 = __half22float2(*reinterpret_cast<const __half2*>(&p1.y));
        acc.x += w1 * f01.x; acc.y += w1 * f01.y; acc.z += w1 * f23.x; acc.w += w1 * f23.y;
        f01 = __half22float2(*reinterpret_cast<const __half2*>(&p2.x));
        f23 = __half22float2(*reinterpret_cast<const __half2*>(&p2.y));
        acc.x += w2 * f01.x; acc.y += w2 * f01.y; acc.z += w2 * f23.x; acc.w += w2 * f23.y;
        f01 = __half22float2(*reinterpret_cast<const __half2*>(&p3.x));
        f23 = __half22float2(*reinterpret_cast<const __half2*>(&p3.y));
        acc.x += w3 * f01.x; acc.y += w3 * f01.y; acc.z += w3 * f23.x; acc.w += w3 * f23.y;
    }
    for (; e < end2; e++) {
        int s = g_csr[e];
        float w = __expf(lrelu(ain + g_aj[s]) - Mi);
        uint2 p = g_oxh[s * 32 + lane];
        float2 f01 = __half22float2(*reinterpret_cast<const __half2*>(&p.x));
        float2 f23 = __half22float2(*reinterpret_cast<const __half2*>(&p.y));
        denom += w;
        acc.x += w * f01.x; acc.y += w * f01.y; acc.z += w * f23.x; acc.w += w * f23.y;
    }
    float inv = 1.f / (denom + 1e-16f);
    acc.x *= inv; acc.y *= inv; acc.z *= inv; acc.w *= inv;
    ((float4*)out)[node * 32 + lane] = acc;
}

// ---------------- launch ----------------
extern "C" void kernel_launch(void* const* d_in, const int* in_sizes, int n_in,
                              void* d_out, int out_size) {
    const float* x = nullptr;
    const int* ei = nullptr;
    const int* label = nullptr;
    const float* W = nullptr;
    const float* att = nullptr;
    for (int i = 0; i < n_in; i++) {
        switch (in_sizes[i]) {
            case N_NODES * DD:   x     = (const float*)d_in[i]; break;
            case 2 * N_EDGES:    ei    = (const int*)d_in[i];   break;
            case N_NODES:        label = (const int*)d_in[i];   break;
            case WSZ:            W     = (const float*)d_in[i]; break;
            case 2 * DD:         att   = (const float*)d_in[i]; break;
            default: break;
        }
    }
    float* out = (float*)d_out;

    k_init <<<(WSZ + 255) / 256, 256>>>(W);
    k_count<<<(N_EDGES + 255) / 256, 256>>>(ei, label);
    k_scan <<<1, 1024>>>();
    k_build<<<(ET + 255) / 256, 256>>>(ei, label);
    k_ox   <<<dim3((N_NODES + 63) / 64, NLAB), 128>>>(x, att);
    k_agg  <<<(N_NODES * 32 + 255) / 256, 256>>>(out);
}

// round 4
// speedup vs baseline: 1.0625x; 1.0625x over previous
#include <cuda_runtime.h>
#include <cuda_fp16.h>

#define N_NODES 50000
#define N_EDGES 800000
#define DD 128
#define NEG 0.2f
#define NLAB 8
#define ET (N_EDGES + N_NODES)
#define WSZ (7 * DD * DD)

// ---------------- device scratch (no allocs allowed) ----------------
__device__ __align__(16) uint2 g_oxh[N_NODES * 32];  // fp16x4 packed transformed features
__device__ float g_ai[N_NODES];
__device__ float g_aj[N_NODES];
__device__ unsigned g_ajmax_u;                       // ordered-uint encoded max(aj)
__device__ int   g_order[N_NODES];
__device__ int   g_counts[NLAB];
__device__ int   g_base[NLAB + 1];
__device__ int   g_lcur[NLAB];
__device__ int   g_deg[N_NODES];
__device__ int   g_off[N_NODES + 1];
__device__ int   g_cur[N_NODES];
__device__ int   g_csr[ET];

__device__ __forceinline__ unsigned fenc(float f) {
    unsigned u = __float_as_uint(f);
    return (u & 0x80000000u) ? ~u : (u | 0x80000000u);
}
__device__ __forceinline__ float fdec(unsigned u) {
    return (u & 0x80000000u) ? __uint_as_float(u ^ 0x80000000u)
                             : __uint_as_float(~u);
}
__device__ __forceinline__ float lrelu(float a) { return a > 0.f ? a : NEG * a; }

// ---------------- init ----------------
__global__ void k_init() {
    int i = blockIdx.x * blockDim.x + threadIdx.x;
    if (i < NLAB) g_counts[i] = 0;
    if (i == NLAB) g_ajmax_u = 0u;   // encodes -inf
    if (i < N_NODES) g_deg[i] = 1;   // self loop pre-counted
}

// label histogram (warp-aggregated) + in-degree count
__global__ void k_count(const int* __restrict__ ei, const int* __restrict__ label) {
    int i = blockIdx.x * blockDim.x + threadIdx.x;
    if (i < N_NODES) {
        int lb = label[i];
        if (lb < 1 || lb > 7) lb = 0;
        unsigned act = __activemask();
        unsigned peers = __match_any_sync(act, lb);
        int leader = __ffs(peers) - 1;
        if ((int)(threadIdx.x & 31) == leader)
            atomicAdd(&g_counts[lb], __popc(peers));
    }
    if (i < N_EDGES) {
        atomicAdd(&g_deg[ei[N_EDGES + i]], 1);  // dst
    }
}

// single block: label bases + exclusive scan of degrees
__global__ void k_scan() {
    __shared__ int ssum[1024];
    int t = threadIdx.x;
    if (t == 0) {
        int b = 0;
        for (int k = 0; k < NLAB; k++) { g_base[k] = b; g_lcur[k] = b; b += g_counts[k]; }
        g_base[NLAB] = b;
    }
    const int CH = (N_NODES + 1023) / 1024;  // 49
    int b0 = t * CH;
    int s = 0;
    for (int i = 0; i < CH; i++) {
        int idx = b0 + i;
        if (idx < N_NODES) s += g_deg[idx];
    }
    ssum[t] = s;
    __syncthreads();
    for (int off = 1; off < 1024; off <<= 1) {
        int v = (t >= off) ? ssum[t - off] : 0;
        __syncthreads();
        ssum[t] += v;
        __syncthreads();
    }
    int run = (t == 0) ? 0 : ssum[t - 1];
    for (int i = 0; i < CH; i++) {
        int idx = b0 + i;
        if (idx < N_NODES) {
            g_off[idx] = run;
            g_cur[idx] = run;
            run += g_deg[idx];
        }
    }
    if (t == 1023) g_off[N_NODES] = ssum[1023];
}

// fused: label-group scatter (i < N) + CSR fill (i < ET)
__global__ void k_build(const int* __restrict__ ei, const int* __restrict__ label) {
    int i = blockIdx.x * blockDim.x + threadIdx.x;
    if (i < N_NODES) {
        int lb = label[i];
        if (lb < 1 || lb > 7) lb = 0;
        unsigned act = __activemask();
        unsigned peers = __match_any_sync(act, lb);
        int leader = __ffs(peers) - 1;
        int lane = threadIdx.x & 31;
        int rank = __popc(peers & ((1u << lane) - 1u));
        int basePos = 0;
        if (lane == leader) basePos = atomicAdd(&g_lcur[lb], __popc(peers));
        basePos = __shfl_sync(act, basePos, leader);
        g_order[basePos + rank] = i;
    }
    if (i < N_EDGES) {
        int s = ei[i];
        int d = ei[N_EDGES + i];
        int pos = atomicAdd(&g_cur[d], 1);
        g_csr[pos] = s;
    } else if (i < ET) {
        int n = i - N_EDGES;
        int pos = atomicAdd(&g_cur[n], 1);
        g_csr[pos] = n;
    }
}

// label-grouped FFMA tile GEMM + fused epilogue (round-2 kernel + ajmax):
//   r = x + W[k-1]^T x ;  g_oxh = half(r) ;  g_ai/g_aj = r.att dots ; ajmax
__global__ void __launch_bounds__(128) k_ox(const float* __restrict__ x,
                                            const float* __restrict__ W,
                                            const float* __restrict__ att) {
    int k = blockIdx.y;
    int gbase = g_base[k];
    int start = gbase + blockIdx.x * 32;
    int end   = gbase + g_counts[k];
    if (start >= end) return;
    int nEff = min(32, end - start);

    __shared__ float xs[32 * DD];
    __shared__ int nid[32];
    int tid = threadIdx.x;
    if (tid < 32) nid[tid] = (tid < nEff) ? g_order[start + tid] : g_order[start];
    __syncthreads();

    const float4* x4 = (const float4*)x;
    float4* xs4 = (float4*)xs;
    for (int idx = tid; idx < 32 * 32; idx += 128) {
        int j = idx >> 5, d4 = idx & 31;
        xs4[j * 32 + d4] = (j < nEff) ? x4[nid[j] * 32 + d4]
                                      : make_float4(0.f, 0.f, 0.f, 0.f);
    }
    __syncthreads();

    int o4 = tid & 31;   // output float4 index (channels 4*o4..4*o4+3)
    int jg = tid >> 5;   // warp jg owns nodes {jg, jg+4, ..., jg+28}

    float4 acc[8];
#pragma unroll
    for (int jj = 0; jj < 8; jj++) acc[jj] = make_float4(0.f, 0.f, 0.f, 0.f);

    if (k > 0) {
        const float4* W4 = (const float4*)(W + (size_t)(k - 1) * DD * DD);
        for (int d4 = 0; d4 < 32; d4++) {
            float4 w0 = W4[(d4 * 4 + 0) * 32 + o4];
            float4 w1 = W4[(d4 * 4 + 1) * 32 + o4];
            float4 w2 = W4[(d4 * 4 + 2) * 32 + o4];
            float4 w3 = W4[(d4 * 4 + 3) * 32 + o4];
#pragma unroll
            for (int jj = 0; jj < 8; jj++) {
                float4 xv = xs4[(jg + jj * 4) * 32 + d4];  // LDS.128 broadcast
                acc[jj].x += xv.x * w0.x + xv.y * w1.x + xv.z * w2.x + xv.w * w3.x;
                acc[jj].y += xv.x * w0.y + xv.y * w1.y + xv.z * w2.y + xv.w * w3.y;
                acc[jj].z += xv.x * w0.z + xv.y * w1.z + xv.z * w2.z + xv.w * w3.z;
                acc[jj].w += xv.x * w0.w + xv.y * w1.w + xv.z * w2.w + xv.w * w3.w;
            }
        }
    }

    float4 a4 = ((const float4*)att)[o4];
    float4 b4 = ((const float4*)att)[32 + o4];

#pragma unroll
    for (int jj = 0; jj < 8; jj++) {
        int j = jg + jj * 4;
        float4 xv = xs4[j * 32 + o4];
        float4 r = make_float4(xv.x + acc[jj].x, xv.y + acc[jj].y,
                               xv.z + acc[jj].z, xv.w + acc[jj].w);
        // attention dots (fp32, pre-rounding) — warp-reduce
        float si = r.x * a4.x + r.y * a4.y + r.z * a4.z + r.w * a4.w;
        float sj = r.x * b4.x + r.y * b4.y + r.z * b4.z + r.w * b4.w;
#pragma unroll
        for (int o = 16; o; o >>= 1) {
            si += __shfl_xor_sync(0xFFFFFFFFu, si, o);
            sj += __shfl_xor_sync(0xFFFFFFFFu, sj, o);
        }
        if (j < nEff) {
            int node = nid[j];
            __half2 h01 = __floats2half2_rn(r.x, r.y);
            __half2 h23 = __floats2half2_rn(r.z, r.w);
            uint2 pk;
            pk.x = *reinterpret_cast<unsigned*>(&h01);
            pk.y = *reinterpret_cast<unsigned*>(&h23);
            g_oxh[node * 32 + o4] = pk;
            if (o4 == 0) {
                g_ai[node] = si;
                g_aj[node] = sj;
                atomicMax(&g_ajmax_u, fenc(sj));
            }
        }
    }
}

// warp per dst node: single-pass softmax (global aj-max bound) + fp16 gather
__global__ void __launch_bounds__(256) k_agg(float* __restrict__ out) {
    int node = (blockIdx.x * blockDim.x + threadIdx.x) >> 5;
    int lane = threadIdx.x & 31;
    if (node >= N_NODES) return;
    int beg = g_off[node], end2 = g_off[node + 1];
    float ain = g_ai[node];
    float Mi = lrelu(ain + fdec(g_ajmax_u));  // upper bound on all alphas of this node

    float4 acc = make_float4(0.f, 0.f, 0.f, 0.f);
    float denom = 0.f;
    int e = beg;
    for (; e + 4 <= end2; e += 4) {
        int s0 = g_csr[e], s1 = g_csr[e + 1], s2 = g_csr[e + 2], s3 = g_csr[e + 3];
        float w0 = __expf(lrelu(ain + g_aj[s0]) - Mi);
        float w1 = __expf(lrelu(ain + g_aj[s1]) - Mi);
        float w2 = __expf(lrelu(ain + g_aj[s2]) - Mi);
        float w3 = __expf(lrelu(ain + g_aj[s3]) - Mi);
        uint2 p0 = g_oxh[s0 * 32 + lane];
        uint2 p1 = g_oxh[s1 * 32 + lane];
        uint2 p2 = g_oxh[s2 * 32 + lane];
        uint2 p3 = g_oxh[s3 * 32 + lane];
        denom += (w0 + w1) + (w2 + w3);
        float2 f01, f23;
        f01 = __half22float2(*reinterpret_cast<const __half2*>(&p0.x));
        f23 = __half22float2(*reinterpret_cast<const __half2*>(&p0.y));
        acc.x += w0 * f01.x; acc.y += w0 * f01.y; acc.z += w0 * f23.x; acc.w += w0 * f23.y;
        f01 = __half22float2(*reinterpret_cast<const __half2*>(&p1.x));
        f23 = __half22float2(*reinterpret_cast<const __half2*>(&p1.y));
        acc.x += w1 * f01.x; acc.y += w1 * f01.y; acc.z += w1 * f23.x; acc.w += w1 * f23.y;
        f01 = __half22float2(*reinterpret_cast<const __half2*>(&p2.x));
        f23 = __half22float2(*reinterpret_cast<const __half2*>(&p2.y));
        acc.x += w2 * f01.x; acc.y += w2 * f01.y; acc.z += w2 * f23.x; acc.w += w2 * f23.y;
        f01 = __half22float2(*reinterpret_cast<const __half2*>(&p3.x));
        f23 = __half22float2(*reinterpret_cast<const __half2*>(&p3.y));
        acc.x += w3 * f01.x; acc.y += w3 * f01.y; acc.z += w3 * f23.x; acc.w += w3 * f23.y;
    }
    for (; e < end2; e++) {
        int s = g_csr[e];
        float w = __expf(lrelu(ain + g_aj[s]) - Mi);
        uint2 p = g_oxh[s * 32 + lane];
        float2 f01 = __half22float2(*reinterpret_cast<const __half2*>(&p.x));
        float2 f23 = __half22float2(*reinterpret_cast<const __half2*>(&p.y));
        denom += w;
        acc.x += w * f01.x; acc.y += w * f01.y; acc.z += w * f23.x; acc.w += w * f23.y;
    }
    float inv = 1.f / (denom + 1e-16f);
    acc.x *= inv; acc.y *= inv; acc.z *= inv; acc.w *= inv;
    ((float4*)out)[node * 32 + lane] = acc;
}

// ---------------- launch ----------------
extern "C" void kernel_launch(void* const* d_in, const int* in_sizes, int n_in,
                              void* d_out, int out_size) {
    const float* x = nullptr;
    const int* ei = nullptr;
    const int* label = nullptr;
    const float* W = nullptr;
    const float* att = nullptr;
    for (int i = 0; i < n_in; i++) {
        switch (in_sizes[i]) {
            case N_NODES * DD:   x     = (const float*)d_in[i]; break;
            case 2 * N_EDGES:    ei    = (const int*)d_in[i];   break;
            case N_NODES:        label = (const int*)d_in[i];   break;
            case WSZ:            W     = (const float*)d_in[i]; break;
            case 2 * DD:         att   = (const float*)d_in[i]; break;
            default: break;
        }
    }
    float* out = (float*)d_out;

    k_init <<<(N_NODES + 255) / 256, 256>>>();
    k_count<<<(N_EDGES + 255) / 256, 256>>>(ei, label);
    k_scan <<<1, 1024>>>();
    k_build<<<(ET + 255) / 256, 256>>>(ei, label);
    k_ox   <<<dim3((N_NODES + 31) / 32, NLAB), 128>>>(x, W, att);
    k_agg  <<<(N_NODES * 32 + 255) / 256, 256>>>(out);
}

// round 5
// speedup vs baseline: 1.6145x; 1.5195x over previous
#include <cuda_runtime.h>
#include <cuda_fp16.h>

#define N_NODES 50000
#define N_EDGES 800000
#define DD 128
#define NEG 0.2f
#define NLAB 8
#define ET (N_EDGES + N_NODES)
#define WSZ (7 * DD * DD)
#define NB_SCAN 49   // ceil(50000/1024)

// ---------------- device scratch (no allocs allowed) ----------------
__device__ __align__(16) uint2 g_oxh[N_NODES * 32];  // fp16x4 packed transformed features
__device__ float g_ai[N_NODES];
__device__ float g_aj[N_NODES];
__device__ unsigned g_ajmax_u;                       // ordered-uint encoded max(aj)
__device__ int   g_order[N_NODES];
__device__ int   g_counts[NLAB];
__device__ int   g_base[NLAB + 1];
__device__ int   g_lcur[NLAB];
__device__ int   g_deg[N_NODES];
__device__ int   g_off[N_NODES + 1];
__device__ int   g_cur[N_NODES];
__device__ int   g_csr[ET];
__device__ int   g_part[NB_SCAN];
__device__ int   g_pscan[NB_SCAN];

__device__ __forceinline__ unsigned fenc(float f) {
    unsigned u = __float_as_uint(f);
    return (u & 0x80000000u) ? ~u : (u | 0x80000000u);
}
__device__ __forceinline__ float fdec(unsigned u) {
    return (u & 0x80000000u) ? __uint_as_float(u ^ 0x80000000u)
                             : __uint_as_float(~u);
}
__device__ __forceinline__ float lrelu(float a) { return a > 0.f ? a : NEG * a; }

// ---------------- init ----------------
__global__ void k_init() {
    int i = blockIdx.x * blockDim.x + threadIdx.x;
    if (i < NLAB) g_counts[i] = 0;
    if (i == NLAB) g_ajmax_u = 0u;   // encodes -inf
    if (i < N_NODES) g_deg[i] = 1;   // self loop pre-counted
}

// label histogram (warp-aggregated) + in-degree count
__global__ void k_count(const int* __restrict__ ei, const int* __restrict__ label) {
    int i = blockIdx.x * blockDim.x + threadIdx.x;
    if (i < N_NODES) {
        int lb = label[i];
        if (lb < 1 || lb > 7) lb = 0;
        unsigned act = __activemask();
        unsigned peers = __match_any_sync(act, lb);
        int leader = __ffs(peers) - 1;
        if ((int)(threadIdx.x & 31) == leader)
            atomicAdd(&g_counts[lb], __popc(peers));
    }
    if (i < N_EDGES) {
        atomicAdd(&g_deg[ei[N_EDGES + i]], 1);  // dst
    }
}

// stage 1: coalesced per-block sums of g_deg
__global__ void __launch_bounds__(1024) k_part() {
    __shared__ int wsum[32];
    int t = threadIdx.x, b = blockIdx.x;
    int idx = b * 1024 + t;
    int v = (idx < N_NODES) ? g_deg[idx] : 0;
#pragma unroll
    for (int o = 16; o; o >>= 1) v += __shfl_xor_sync(0xFFFFFFFFu, v, o);
    if ((t & 31) == 0) wsum[t >> 5] = v;
    __syncthreads();
    if (t < 32) {
        int s = wsum[t];
#pragma unroll
        for (int o = 16; o; o >>= 1) s += __shfl_xor_sync(0xFFFFFFFFu, s, o);
        if (t == 0) g_part[b] = s;
    }
}

// stage 2: tiny serial scans (49 partials + 8 label bases)
__global__ void k_mid() {
    if (threadIdx.x == 0) {
        int b = 0;
        for (int k = 0; k < NLAB; k++) { g_base[k] = b; g_lcur[k] = b; b += g_counts[k]; }
        g_base[NLAB] = b;
        int r = 0;
        for (int i = 0; i < NB_SCAN; i++) { g_pscan[i] = r; r += g_part[i]; }
    }
}

// stage 3: block-local exclusive scan + partial base -> g_off / g_cur (coalesced)
__global__ void __launch_bounds__(1024) k_off() {
    __shared__ int wsum[32];
    int t = threadIdx.x, b = blockIdx.x;
    int lane = t & 31, wid = t >> 5;
    int idx = b * 1024 + t;
    int v = (idx < N_NODES) ? g_deg[idx] : 0;
    // intra-warp inclusive scan
    int s = v;
#pragma unroll
    for (int o = 1; o < 32; o <<= 1) {
        int u = __shfl_up_sync(0xFFFFFFFFu, s, o);
        if (lane >= o) s += u;
    }
    if (lane == 31) wsum[wid] = s;
    __syncthreads();
    if (t < 32) {
        int u = wsum[t];
        int ss = u;
#pragma unroll
        for (int o = 1; o < 32; o <<= 1) {
            int q = __shfl_up_sync(0xFFFFFFFFu, ss, o);
            if (t >= o) ss += q;
        }
        wsum[t] = ss - u;   // exclusive warp offset
    }
    __syncthreads();
    int excl = (s - v) + wsum[wid] + g_pscan[b];
    if (idx < N_NODES) { g_off[idx] = excl; g_cur[idx] = excl; }
    if (idx == N_NODES) g_off[N_NODES] = excl;   // total (tail vs are 0)
}

// fused: label-group scatter (i < N) + CSR fill (i < ET)
__global__ void k_build(const int* __restrict__ ei, const int* __restrict__ label) {
    int i = blockIdx.x * blockDim.x + threadIdx.x;
    if (i < N_NODES) {
        int lb = label[i];
        if (lb < 1 || lb > 7) lb = 0;
        unsigned act = __activemask();
        unsigned peers = __match_any_sync(act, lb);
        int leader = __ffs(peers) - 1;
        int lane = threadIdx.x & 31;
        int rank = __popc(peers & ((1u << lane) - 1u));
        int basePos = 0;
        if (lane == leader) basePos = atomicAdd(&g_lcur[lb], __popc(peers));
        basePos = __shfl_sync(act, basePos, leader);
        g_order[basePos + rank] = i;
    }
    if (i < N_EDGES) {
        int s = ei[i];
        int d = ei[N_EDGES + i];
        int pos = atomicAdd(&g_cur[d], 1);
        g_csr[pos] = s;
    } else if (i < ET) {
        int n = i - N_EDGES;
        int pos = atomicAdd(&g_cur[n], 1);
        g_csr[pos] = n;
    }
}

// label-grouped FFMA tile GEMM + fused epilogue:
//   r = x + W[k-1]^T x ;  g_oxh = half(r) ;  g_ai/g_aj = r.att dots ; ajmax
__global__ void __launch_bounds__(128) k_ox(const float* __restrict__ x,
                                            const float* __restrict__ W,
                                            const float* __restrict__ att) {
    int k = blockIdx.y;
    int gbase = g_base[k];
    int start = gbase + blockIdx.x * 32;
    int end   = gbase + g_counts[k];
    if (start >= end) return;
    int nEff = min(32, end - start);

    __shared__ float xs[32 * DD];
    __shared__ int nid[32];
    int tid = threadIdx.x;
    if (tid < 32) nid[tid] = (tid < nEff) ? g_order[start + tid] : g_order[start];
    __syncthreads();

    const float4* x4 = (const float4*)x;
    float4* xs4 = (float4*)xs;
    for (int idx = tid; idx < 32 * 32; idx += 128) {
        int j = idx >> 5, d4 = idx & 31;
        xs4[j * 32 + d4] = (j < nEff) ? x4[nid[j] * 32 + d4]
                                      : make_float4(0.f, 0.f, 0.f, 0.f);
    }
    __syncthreads();

    int o4 = tid & 31;   // output float4 index (channels 4*o4..4*o4+3)
    int jg = tid >> 5;   // warp jg owns nodes {jg, jg+4, ..., jg+28}

    float4 acc[8];
#pragma unroll
    for (int jj = 0; jj < 8; jj++) acc[jj] = make_float4(0.f, 0.f, 0.f, 0.f);

    if (k > 0) {
        const float4* W4 = (const float4*)(W + (size_t)(k - 1) * DD * DD);
        for (int d4 = 0; d4 < 32; d4++) {
            float4 w0 = W4[(d4 * 4 + 0) * 32 + o4];
            float4 w1 = W4[(d4 * 4 + 1) * 32 + o4];
            float4 w2 = W4[(d4 * 4 + 2) * 32 + o4];
            float4 w3 = W4[(d4 * 4 + 3) * 32 + o4];
#pragma unroll
            for (int jj = 0; jj < 8; jj++) {
                float4 xv = xs4[(jg + jj * 4) * 32 + d4];  // LDS.128 broadcast
                acc[jj].x += xv.x * w0.x + xv.y * w1.x + xv.z * w2.x + xv.w * w3.x;
                acc[jj].y += xv.x * w0.y + xv.y * w1.y + xv.z * w2.y + xv.w * w3.y;
                acc[jj].z += xv.x * w0.z + xv.y * w1.z + xv.z * w2.z + xv.w * w3.z;
                acc[jj].w += xv.x * w0.w + xv.y * w1.w + xv.z * w2.w + xv.w * w3.w;
            }
        }
    }

    float4 a4 = ((const float4*)att)[o4];
    float4 b4 = ((const float4*)att)[32 + o4];

#pragma unroll
    for (int jj = 0; jj < 8; jj++) {
        int j = jg + jj * 4;
        float4 xv = xs4[j * 32 + o4];
        float4 r = make_float4(xv.x + acc[jj].x, xv.y + acc[jj].y,
                               xv.z + acc[jj].z, xv.w + acc[jj].w);
        float si = r.x * a4.x + r.y * a4.y + r.z * a4.z + r.w * a4.w;
        float sj = r.x * b4.x + r.y * b4.y + r.z * b4.z + r.w * b4.w;
#pragma unroll
        for (int o = 16; o; o >>= 1) {
            si += __shfl_xor_sync(0xFFFFFFFFu, si, o);
            sj += __shfl_xor_sync(0xFFFFFFFFu, sj, o);
        }
        if (j < nEff) {
            int node = nid[j];
            __half2 h01 = __floats2half2_rn(r.x, r.y);
            __half2 h23 = __floats2half2_rn(r.z, r.w);
            uint2 pk;
            pk.x = *reinterpret_cast<unsigned*>(&h01);
            pk.y = *reinterpret_cast<unsigned*>(&h23);
            g_oxh[node * 32 + o4] = pk;
            if (o4 == 0) {
                g_ai[node] = si;
                g_aj[node] = sj;
                atomicMax(&g_ajmax_u, fenc(sj));
            }
        }
    }
}

// warp per dst node: single-pass softmax (global aj-max bound) + fp16 gather
__global__ void __launch_bounds__(256) k_agg(float* __restrict__ out) {
    int node = (blockIdx.x * blockDim.x + threadIdx.x) >> 5;
    int lane = threadIdx.x & 31;
    if (node >= N_NODES) return;
    int beg = g_off[node], end2 = g_off[node + 1];
    float ain = g_ai[node];
    float Mi = lrelu(ain + fdec(g_ajmax_u));  // upper bound on all alphas of this node

    float4 acc = make_float4(0.f, 0.f, 0.f, 0.f);
    float denom = 0.f;
    int e = beg;
    for (; e + 4 <= end2; e += 4) {
        int s0 = g_csr[e], s1 = g_csr[e + 1], s2 = g_csr[e + 2], s3 = g_csr[e + 3];
        float w0 = __expf(lrelu(ain + g_aj[s0]) - Mi);
        float w1 = __expf(lrelu(ain + g_aj[s1]) - Mi);
        float w2 = __expf(lrelu(ain + g_aj[s2]) - Mi);
        float w3 = __expf(lrelu(ain + g_aj[s3]) - Mi);
        uint2 p0 = g_oxh[s0 * 32 + lane];
        uint2 p1 = g_oxh[s1 * 32 + lane];
        uint2 p2 = g_oxh[s2 * 32 + lane];
        uint2 p3 = g_oxh[s3 * 32 + lane];
        denom += (w0 + w1) + (w2 + w3);
        float2 f01, f23;
        f01 = __half22float2(*reinterpret_cast<const __half2*>(&p0.x));
        f23 = __half22float2(*reinterpret_cast<const __half2*>(&p0.y));
        acc.x += w0 * f01.x; acc.y += w0 * f01.y; acc.z += w0 * f23.x; acc.w += w0 * f23.y;
        f01 = __half22float2(*reinterpret_cast<const __half2*>(&p1.x));
        f23 = __half22float2(*reinterpret_cast<const __half2*>(&p1.y));
        acc.x += w1 * f01.x; acc.y += w1 * f01.y; acc.z += w1 * f23.x; acc.w += w1 * f23.y;
        f01 = __half22float2(*reinterpret_cast<const __half2*>(&p2.x));
        f23 = __half22float2(*reinterpret_cast<const __half2*>(&p2.y));
        acc.x += w2 * f01.x; acc.y += w2 * f01.y; acc.z += w2 * f23.x; acc.w += w2 * f23.y;
        f01 = __half22float2(*reinterpret_cast<const __half2*>(&p3.x));
        f23 = __half22float2(*reinterpret_cast<const __half2*>(&p3.y));
        acc.x += w3 * f01.x; acc.y += w3 * f01.y; acc.z += w3 * f23.x; acc.w += w3 * f23.y;
    }
    for (; e < end2; e++) {
        int s = g_csr[e];
        float w = __expf(lrelu(ain + g_aj[s]) - Mi);
        uint2 p = g_oxh[s * 32 + lane];
        float2 f01 = __half22float2(*reinterpret_cast<const __half2*>(&p.x));
        float2 f23 = __half22float2(*reinterpret_cast<const __half2*>(&p.y));
        denom += w;
        acc.x += w * f01.x; acc.y += w * f01.y; acc.z += w * f23.x; acc.w += w * f23.y;
    }
    float inv = 1.f / (denom + 1e-16f);
    acc.x *= inv; acc.y *= inv; acc.z *= inv; acc.w *= inv;
    ((float4*)out)[node * 32 + lane] = acc;
}

// ---------------- launch ----------------
extern "C" void kernel_launch(void* const* d_in, const int* in_sizes, int n_in,
                              void* d_out, int out_size) {
    const float* x = nullptr;
    const int* ei = nullptr;
    const int* label = nullptr;
    const float* W = nullptr;
    const float* att = nullptr;
    for (int i = 0; i < n_in; i++) {
        switch (in_sizes[i]) {
            case N_NODES * DD:   x     = (const float*)d_in[i]; break;
            case 2 * N_EDGES:    ei    = (const int*)d_in[i];   break;
            case N_NODES:        label = (const int*)d_in[i];   break;
            case WSZ:            W     = (const float*)d_in[i]; break;
            case 2 * DD:         att   = (const float*)d_in[i]; break;
            default: break;
        }
    }
    float* out = (float*)d_out;

    k_init <<<(N_NODES + 255) / 256, 256>>>();
    k_count<<<(N_EDGES + 255) / 256, 256>>>(ei, label);
    k_part <<<NB_SCAN, 1024>>>();
    k_mid  <<<1, 32>>>();
    k_off  <<<NB_SCAN, 1024>>>();
    k_build<<<(ET + 255) / 256, 256>>>(ei, label);
    k_ox   <<<dim3((N_NODES + 31) / 32, NLAB), 128>>>(x, W, att);
    k_agg  <<<(N_NODES * 32 + 255) / 256, 256>>>(out);
}

// round 7
// speedup vs baseline: 2.2905x; 1.4187x over previous
#include <cuda_runtime.h>
#include <cuda_fp16.h>

#define N_NODES 50000
#define N_EDGES 800000
#define DD 128
#define NEG 0.2f
#define NLAB 8
#define ET (N_EDGES + N_NODES)
#define WSZ (7 * DD * DD)
#define NB_SCAN 49   // ceil(50000/1024)
#define XP 136       // padded smem row stride (halfs): 272B -> +4 banks/row, conflict-free

// ---------------- device scratch (no allocs allowed) ----------------
__device__ __align__(16) uint2 g_oxh[N_NODES * 32];  // fp16x4 packed transformed features
__device__ __align__(16) __half g_Wh[WSZ];           // fp16 weights
__device__ float g_ai[N_NODES];
__device__ float g_aj[N_NODES];
__device__ unsigned g_ajmax_u;                       // ordered-uint encoded max(aj)
__device__ int   g_order[N_NODES];
__device__ int   g_counts[NLAB];
__device__ int   g_base[NLAB + 1];
__device__ int   g_lcur[NLAB];
__device__ int   g_deg[N_NODES];
__device__ int   g_off[N_NODES + 1];
__device__ int   g_cur[N_NODES];
__device__ int   g_csr[ET];
__device__ int   g_part[NB_SCAN];
__device__ int   g_pscan[NB_SCAN];

__device__ __forceinline__ unsigned fenc(float f) {
    unsigned u = __float_as_uint(f);
    return (u & 0x80000000u) ? ~u : (u | 0x80000000u);
}
__device__ __forceinline__ float fdec(unsigned u) {
    return (u & 0x80000000u) ? __uint_as_float(u ^ 0x80000000u)
                             : __uint_as_float(~u);
}
__device__ __forceinline__ float lrelu(float a) { return a > 0.f ? a : NEG * a; }

// ---------------- init: counters, degrees, W->fp16 ----------------
__global__ void k_init(const float* __restrict__ W) {
    int i = blockIdx.x * blockDim.x + threadIdx.x;
    if (i < NLAB) g_counts[i] = 0;
    if (i == NLAB) g_ajmax_u = 0u;   // encodes -inf
    if (i < N_NODES) g_deg[i] = 1;   // self loop pre-counted
    if (i < WSZ) g_Wh[i] = __float2half_rn(W[i]);
}

// label histogram (warp-aggregated) + in-degree count
__global__ void k_count(const int* __restrict__ ei, const int* __restrict__ label) {
    int i = blockIdx.x * blockDim.x + threadIdx.x;
    if (i < N_NODES) {
        int lb = label[i];
        if (lb < 1 || lb > 7) lb = 0;
        unsigned act = __activemask();
        unsigned peers = __match_any_sync(act, lb);
        int leader = __ffs(peers) - 1;
        if ((int)(threadIdx.x & 31) == leader)
            atomicAdd(&g_counts[lb], __popc(peers));
    }
    if (i < N_EDGES) {
        atomicAdd(&g_deg[ei[N_EDGES + i]], 1);  // dst
    }
}

// stage 1: coalesced per-block sums of g_deg
__global__ void __launch_bounds__(1024) k_part() {
    __shared__ int wsum[32];
    int t = threadIdx.x, b = blockIdx.x;
    int idx = b * 1024 + t;
    int v = (idx < N_NODES) ? g_deg[idx] : 0;
#pragma unroll
    for (int o = 16; o; o >>= 1) v += __shfl_xor_sync(0xFFFFFFFFu, v, o);
    if ((t & 31) == 0) wsum[t >> 5] = v;
    __syncthreads();
    if (t < 32) {
        int s = wsum[t];
#pragma unroll
        for (int o = 16; o; o >>= 1) s += __shfl_xor_sync(0xFFFFFFFFu, s, o);
        if (t == 0) g_part[b] = s;
    }
}

// stage 2: tiny serial scans (49 partials + 8 label bases)
__global__ void k_mid() {
    if (threadIdx.x == 0) {
        int b = 0;
        for (int k = 0; k < NLAB; k++) { g_base[k] = b; g_lcur[k] = b; b += g_counts[k]; }
        g_base[NLAB] = b;
        int r = 0;
        for (int i = 0; i < NB_SCAN; i++) { g_pscan[i] = r; r += g_part[i]; }
    }
}

// stage 3: block-local exclusive scan + partial base -> g_off / g_cur (coalesced)
__global__ void __launch_bounds__(1024) k_off() {
    __shared__ int wsum[32];
    int t = threadIdx.x, b = blockIdx.x;
    int lane = t & 31, wid = t >> 5;
    int idx = b * 1024 + t;
    int v = (idx < N_NODES) ? g_deg[idx] : 0;
    int s = v;
#pragma unroll
    for (int o = 1; o < 32; o <<= 1) {
        int u = __shfl_up_sync(0xFFFFFFFFu, s, o);
        if (lane >= o) s += u;
    }
    if (lane == 31) wsum[wid] = s;
    __syncthreads();
    if (t < 32) {
        int u = wsum[t];
        int ss = u;
#pragma unroll
        for (int o = 1; o < 32; o <<= 1) {
            int q = __shfl_up_sync(0xFFFFFFFFu, ss, o);
            if (t >= o) ss += q;
        }
        wsum[t] = ss - u;   // exclusive warp offset
    }
    __syncthreads();
    int excl = (s - v) + wsum[wid] + g_pscan[b];
    if (idx < N_NODES) { g_off[idx] = excl; g_cur[idx] = excl; }
    if (idx == N_NODES) g_off[N_NODES] = excl;
}

// fused: label-group scatter (i < N) + CSR fill (i < ET)
__global__ void k_build(const int* __restrict__ ei, const int* __restrict__ label) {
    int i = blockIdx.x * blockDim.x + threadIdx.x;
    if (i < N_NODES) {
        int lb = label[i];
        if (lb < 1 || lb > 7) lb = 0;
        unsigned act = __activemask();
        unsigned peers = __match_any_sync(act, lb);
        int leader = __ffs(peers) - 1;
        int lane = threadIdx.x & 31;
        int rank = __popc(peers & ((1u << lane) - 1u));
        int basePos = 0;
        if (lane == leader) basePos = atomicAdd(&g_lcur[lb], __popc(peers));
        basePos = __shfl_sync(act, basePos, leader);
        g_order[basePos + rank] = i;
    }
    if (i < N_EDGES) {
        int s = ei[i];
        int d = ei[N_EDGES + i];
        int pos = atomicAdd(&g_cur[d], 1);
        g_csr[pos] = s;
    } else if (i < ET) {
        int n = i - N_EDGES;
        int pos = atomicAdd(&g_cur[n], 1);
        g_csr[pos] = n;
    }
}

// tensor-core label-grouped GEMM (64 nodes x 128 out / block) with
// fragment-native epilogue: half2 direct store, quad-shuffle ai/aj dots.
__global__ void __launch_bounds__(128) k_ox(const float* __restrict__ x,
                                            const float* __restrict__ att) {
    int k = blockIdx.y;
    int gbase = g_base[k];
    int start = gbase + blockIdx.x * 64;
    int end   = gbase + g_counts[k];
    if (start >= end) return;
    int nEff = min(64, end - start);

    __shared__ __align__(16) __half xs[64 * XP];     // padded node tile
    __shared__ __align__(16) __half ws[64 * XP];     // padded W chunk (64 k-rows)
    __shared__ float att_s[2 * DD];
    __shared__ int nid[64];
    __shared__ unsigned s_ajmax;

    int tid = threadIdx.x;
    int lane = tid & 31, wid = tid >> 5;
    if (tid < 64) nid[tid] = (tid < nEff) ? g_order[start + tid] : g_order[start];
    for (int t2 = tid; t2 < 2 * DD; t2 += 128) att_s[t2] = att[t2];  // FIX: cover all 256
    if (tid == 0) s_ajmax = 0u;
    __syncthreads();

    // stage x rows (fp32 -> fp16, half-row per thread)
    {
        int j = tid >> 1, part = tid & 1;
        const float4* xr = (const float4*)x + (size_t)nid[j] * 32 + part * 16;
        __half2* dst = (__half2*)(xs + j * XP + part * 64);
#pragma unroll
        for (int i = 0; i < 16; i++) {
            float4 v = xr[i];
            dst[i * 2 + 0] = __floats2half2_rn(v.x, v.y);
            dst[i * 2 + 1] = __floats2half2_rn(v.z, v.w);
        }
    }

    float d[16][4];
#pragma unroll
    for (int nt = 0; nt < 16; nt++) { d[nt][0] = d[nt][1] = d[nt][2] = d[nt][3] = 0.f; }

    int wrow0 = wid * 16;  // warp's 16-row strip

    if (k > 0) {
        const __half* Wg = g_Wh + (size_t)(k - 1) * DD * DD;
        for (int c = 0; c < 2; c++) {   // two 64-deep K chunks
            __syncthreads();
            {
                const int4* wsrc = (const int4*)(Wg + (size_t)c * 64 * DD);
                for (int idx = tid; idx < 1024; idx += 128) {
                    int dr = idx >> 4, i = idx & 15;
                    *(int4*)(ws + dr * XP + i * 8) = wsrc[dr * 16 + i];
                }
            }
            __syncthreads();
#pragma unroll
            for (int kt = 0; kt < 4; kt++) {
                int kb = kt * 16;
                unsigned a0, a1, a2, a3;
                {
                    int r  = (lane & 7) + ((lane >> 3) & 1) * 8;
                    int cc = (lane >> 4) * 8;
                    const __half* ap = xs + (wrow0 + r) * XP + (c * 64 + kb + cc);
                    unsigned sa = (unsigned)__cvta_generic_to_shared(ap);
                    asm volatile("ldmatrix.sync.aligned.m8n8.x4.shared.b16 {%0,%1,%2,%3}, [%4];"
                                 : "=r"(a0), "=r"(a1), "=r"(a2), "=r"(a3) : "r"(sa));
                }
#pragma unroll
                for (int np = 0; np < 8; np++) {
                    int n0 = np * 16;
                    unsigned b0, b1, b2, b3;
                    {
                        int kr = kb + (lane & 7) + ((lane >> 3) & 1) * 8;
                        int nc = n0 + (lane >> 4) * 8;
                        const __half* bp = ws + kr * XP + nc;
                        unsigned sb = (unsigned)__cvta_generic_to_shared(bp);
                        asm volatile("ldmatrix.sync.aligned.m8n8.x4.trans.shared.b16 {%0,%1,%2,%3}, [%4];"
                                     : "=r"(b0), "=r"(b1), "=r"(b2), "=r"(b3) : "r"(sb));
                    }
                    asm volatile("mma.sync.aligned.m16n8k16.row.col.f32.f16.f16.f32 "
                                 "{%0,%1,%2,%3}, {%4,%5,%6,%7}, {%8,%9}, {%0,%1,%2,%3};"
                                 : "+f"(d[np*2][0]), "+f"(d[np*2][1]), "+f"(d[np*2][2]), "+f"(d[np*2][3])
                                 : "r"(a0), "r"(a1), "r"(a2), "r"(a3), "r"(b0), "r"(b1));
                    asm volatile("mma.sync.aligned.m16n8k16.row.col.f32.f16.f16.f32 "
                                 "{%0,%1,%2,%3}, {%4,%5,%6,%7}, {%8,%9}, {%0,%1,%2,%3};"
                                 : "+f"(d[np*2+1][0]), "+f"(d[np*2+1][1]), "+f"(d[np*2+1][2]), "+f"(d[np*2+1][3])
                                 : "r"(a0), "r"(a1), "r"(a2), "r"(a3), "r"(b2), "r"(b3));
                }
            }
        }
    }

    // --------- fragment-native epilogue ---------
    // thread owns rows r0 = wrow0 + (lane>>2), r1 = r0+8; cols nt*8 + 2q, +1
    int q  = lane & 3;
    int r0 = wrow0 + (lane >> 2);
    int r1 = r0 + 8;
    int j0ok = (r0 < nEff), j1ok = (r1 < nEff);
    int node0 = nid[r0], node1 = nid[r1];
    __half* oh0 = (__half*)g_oxh + (size_t)node0 * DD;
    __half* oh1 = (__half*)g_oxh + (size_t)node1 * DD;

    float si0 = 0.f, sj0 = 0.f, si1 = 0.f, sj1 = 0.f;
#pragma unroll
    for (int nt = 0; nt < 16; nt++) {
        int cc = nt * 8 + 2 * q;
        float av0 = att_s[cc], av1 = att_s[cc + 1];
        float bv0 = att_s[DD + cc], bv1 = att_s[DD + cc + 1];
        float2 x0 = __half22float2(*(const __half2*)(xs + r0 * XP + cc));
        float2 x1 = __half22float2(*(const __half2*)(xs + r1 * XP + cc));
        float v00 = x0.x + d[nt][0], v01 = x0.y + d[nt][1];
        float v10 = x1.x + d[nt][2], v11 = x1.y + d[nt][3];
        si0 += v00 * av0 + v01 * av1;
        sj0 += v00 * bv0 + v01 * bv1;
        si1 += v10 * av0 + v11 * av1;
        sj1 += v10 * bv0 + v11 * bv1;
        if (j0ok) *(__half2*)(oh0 + cc) = __floats2half2_rn(v00, v01);
        if (j1ok) *(__half2*)(oh1 + cc) = __floats2half2_rn(v10, v11);
    }
    // reduce over the 4 lanes of the quad (disjoint column quarters, same row)
#pragma unroll
    for (int o = 1; o <= 2; o <<= 1) {
        si0 += __shfl_xor_sync(0xFFFFFFFFu, si0, o);
        sj0 += __shfl_xor_sync(0xFFFFFFFFu, sj0, o);
        si1 += __shfl_xor_sync(0xFFFFFFFFu, si1, o);
        sj1 += __shfl_xor_sync(0xFFFFFFFFu, sj1, o);
    }
    if (q == 0) {
        unsigned mx = 0u;
        if (j0ok) { g_ai[node0] = si0; g_aj[node0] = sj0; mx = fenc(sj0); }
        if (j1ok) { g_ai[node1] = si1; g_aj[node1] = sj1; unsigned m1 = fenc(sj1); if (m1 > mx) mx = m1; }
        if (mx) atomicMax(&s_ajmax, mx);
    }
    __syncthreads();
    if (tid == 0 && s_ajmax) atomicMax(&g_ajmax_u, s_ajmax);
}

// warp per dst node: single-pass softmax (global aj-max bound) + fp16 gather
__global__ void __launch_bounds__(256) k_agg(float* __restrict__ out) {
    int node = (blockIdx.x * blockDim.x + threadIdx.x) >> 5;
    int lane = threadIdx.x & 31;
    if (node >= N_NODES) return;
    int beg = g_off[node], end2 = g_off[node + 1];
    float ain = g_ai[node];
    float Mi = lrelu(ain + fdec(g_ajmax_u));  // upper bound on all alphas of this node

    float4 acc = make_float4(0.f, 0.f, 0.f, 0.f);
    float denom = 0.f;
    int e = beg;
    for (; e + 4 <= end2; e += 4) {
        int s0 = g_csr[e], s1 = g_csr[e + 1], s2 = g_csr[e + 2], s3 = g_csr[e + 3];
        float w0 = __expf(lrelu(ain + g_aj[s0]) - Mi);
        float w1 = __expf(lrelu(ain + g_aj[s1]) - Mi);
        float w2 = __expf(lrelu(ain + g_aj[s2]) - Mi);
        float w3 = __expf(lrelu(ain + g_aj[s3]) - Mi);
        uint2 p0 = g_oxh[s0 * 32 + lane];
        uint2 p1 = g_oxh[s1 * 32 + lane];
        uint2 p2 = g_oxh[s2 * 32 + lane];
        uint2 p3 = g_oxh[s3 * 32 + lane];
        denom += (w0 + w1) + (w2 + w3);
        float2 f01, f23;
        f01 = __half22float2(*reinterpret_cast<const __half2*>(&p0.x));
        f23 = __half22float2(*reinterpret_cast<const __half2*>(&p0.y));
        acc.x += w0 * f01.x; acc.y += w0 * f01.y; acc.z += w0 * f23.x; acc.w += w0 * f23.y;
        f01 = __half22float2(*reinterpret_cast<const __half2*>(&p1.x));
        f23 = __half22float2(*reinterpret_cast<const __half2*>(&p1.y));
        acc.x += w1 * f01.x; acc.y += w1 * f01.y; acc.z += w1 * f23.x; acc.w += w1 * f23.y;
        f01 = __half22float2(*reinterpret_cast<const __half2*>(&p2.x));
        f23 = __half22float2(*reinterpret_cast<const __half2*>(&p2.y));
        acc.x += w2 * f01.x; acc.y += w2 * f01.y; acc.z += w2 * f23.x; acc.w += w2 * f23.y;
        f01 = __half22float2(*reinterpret_cast<const __half2*>(&p3.x));
        f23 = __half22float2(*reinterpret_cast<const __half2*>(&p3.y));
        acc.x += w3 * f01.x; acc.y += w3 * f01.y; acc.z += w3 * f23.x; acc.w += w3 * f23.y;
    }
    for (; e < end2; e++) {
        int s = g_csr[e];
        float w = __expf(lrelu(ain + g_aj[s]) - Mi);
        uint2 p = g_oxh[s * 32 + lane];
        float2 f01 = __half22float2(*reinterpret_cast<const __half2*>(&p.x));
        float2 f23 = __half22float2(*reinterpret_cast<const __half2*>(&p.y));
        denom += w;
        acc.x += w * f01.x; acc.y += w * f01.y; acc.z += w * f23.x; acc.w += w * f23.y;
    }
    float inv = 1.f / (denom + 1e-16f);
    acc.x *= inv; acc.y *= inv; acc.z *= inv; acc.w *= inv;
    ((float4*)out)[node * 32 + lane] = acc;
}

// ---------------- launch ----------------
extern "C" void kernel_launch(void* const* d_in, const int* in_sizes, int n_in,
                              void* d_out, int out_size) {
    const float* x = nullptr;
    const int* ei = nullptr;
    const int* label = nullptr;
    const float* W = nullptr;
    const float* att = nullptr;
    for (int i = 0; i < n_in; i++) {
        switch (in_sizes[i]) {
            case N_NODES * DD:   x     = (const float*)d_in[i]; break;
            case 2 * N_EDGES:    ei    = (const int*)d_in[i];   break;
            case N_NODES:        label = (const int*)d_in[i];   break;
            case WSZ:            W     = (const float*)d_in[i]; break;
            case 2 * DD:         att   = (const float*)d_in[i]; break;
            default: break;
        }
    }
    float* out = (float*)d_out;

    k_init <<<(WSZ + 255) / 256, 256>>>(W);
    k_count<<<(N_EDGES + 255) / 256, 256>>>(ei, label);
    k_part <<<NB_SCAN, 1024>>>();
    k_mid  <<<1, 32>>>();
    k_off  <<<NB_SCAN, 1024>>>();
    k_build<<<(ET + 255) / 256, 256>>>(ei, label);
    k_ox   <<<dim3((N_NODES + 63) / 64, NLAB), 128>>>(x, att);
    k_agg  <<<(N_NODES * 32 + 255) / 256, 256>>>(out);
}

// round 8
// speedup vs baseline: 2.3455x; 1.0240x over previous
#include <cuda_runtime.h>
#include <cuda_fp16.h>

#define N_NODES 50000
#define N_EDGES 800000
#define DD 128
#define NEG 0.2f
#define NLAB 8
#define ET (N_EDGES + N_NODES)
#define WSZ (7 * DD * DD)
#define NB_SCAN 49   // ceil(50000/1024)
#define XP 136       // padded smem row stride (halfs): conflict-free

// ---------------- device scratch (no allocs allowed) ----------------
__device__ __align__(16) uint2 g_oxh[N_NODES * 32];  // fp16x4 packed transformed features
__device__ __align__(16) __half g_Wh[WSZ];           // fp16 weights
__device__ float g_ai[N_NODES];
__device__ float g_aj[N_NODES];
__device__ unsigned g_ajmax_u;                       // ordered-uint encoded max(aj)
__device__ int   g_order[N_NODES];
__device__ int   g_counts[NLAB];
__device__ int   g_base[NLAB + 1];
__device__ int   g_lcur[NLAB];                       // relative label cursors (start 0)
__device__ int   g_deg[N_NODES];
__device__ int   g_off[N_NODES + 1];
__device__ int   g_cur[N_NODES];
__device__ int   g_csr[ET];
__device__ int   g_part[NB_SCAN];

__device__ __forceinline__ unsigned fenc(float f) {
    unsigned u = __float_as_uint(f);
    return (u & 0x80000000u) ? ~u : (u | 0x80000000u);
}
__device__ __forceinline__ float fdec(unsigned u) {
    return (u & 0x80000000u) ? __uint_as_float(u ^ 0x80000000u)
                             : __uint_as_float(~u);
}
__device__ __forceinline__ float lrelu(float a) { return a > 0.f ? a : NEG * a; }

// ---------------- init: counters, degrees, W->fp16 ----------------
__global__ void k_init(const float* __restrict__ W) {
    int i = blockIdx.x * blockDim.x + threadIdx.x;
    if (i < NLAB) { g_counts[i] = 0; g_lcur[i] = 0; }
    if (i == NLAB) g_ajmax_u = 0u;   // encodes -inf
    if (i < N_NODES) g_deg[i] = 1;   // self loop pre-counted
    if (i < WSZ) g_Wh[i] = __float2half_rn(W[i]);
}

// label histogram (warp-aggregated) + in-degree count (2 edges/thread)
__global__ void k_count(const int* __restrict__ ei, const int* __restrict__ label) {
    int i = blockIdx.x * blockDim.x + threadIdx.x;
    if (i < N_NODES) {
        int lb = label[i];
        if (lb < 1 || lb > 7) lb = 0;
        unsigned act = __activemask();
        unsigned peers = __match_any_sync(act, lb);
        int leader = __ffs(peers) - 1;
        if ((int)(threadIdx.x & 31) == leader)
            atomicAdd(&g_counts[lb], __popc(peers));
    }
    int e2 = i * 2;
    if (e2 < N_EDGES) {
        int2 d2 = *(const int2*)(ei + N_EDGES + e2);
        atomicAdd(&g_deg[d2.x], 1);
        atomicAdd(&g_deg[d2.y], 1);
    }
}

// stage 1: coalesced per-block sums of g_deg
__global__ void __launch_bounds__(1024) k_part() {
    __shared__ int wsum[32];
    int t = threadIdx.x, b = blockIdx.x;
    int idx = b * 1024 + t;
    int v = (idx < N_NODES) ? g_deg[idx] : 0;
#pragma unroll
    for (int o = 16; o; o >>= 1) v += __shfl_xor_sync(0xFFFFFFFFu, v, o);
    if ((t & 31) == 0) wsum[t >> 5] = v;
    __syncthreads();
    if (t < 32) {
        int s = wsum[t];
#pragma unroll
        for (int o = 16; o; o >>= 1) s += __shfl_xor_sync(0xFFFFFFFFu, s, o);
        if (t == 0) g_part[b] = s;
    }
}

// stage 2 (fused): per-block partial prefix + label bases + node scan -> g_off/g_cur
//                  + label-group scatter of node ids into g_order
__global__ void __launch_bounds__(1024) k_off(const int* __restrict__ label) {
    __shared__ int wsum[32];
    __shared__ int pbase;
    __shared__ int sbase[NLAB];
    int t = threadIdx.x, b = blockIdx.x;
    int lane = t & 31, wid = t >> 5;

    if (t == 0) {               // partial prefix for this block (<=48 adds)
        int r = 0;
        for (int i = 0; i < b; i++) r += g_part[i];
        pbase = r;
    }
    if (t == 32) {              // label bases (same in every block)
        int bb = 0;
        for (int k = 0; k < NLAB; k++) {
            sbase[k] = bb;
            if (b == 0) g_base[k] = bb;   // publish for k_ox
            bb += g_counts[k];
        }
        if (b == 0) g_base[NLAB] = bb;
    }
    __syncthreads();

    int idx = b * 1024 + t;
    int v = (idx < N_NODES) ? g_deg[idx] : 0;
    int s = v;
#pragma unroll
    for (int o = 1; o < 32; o <<= 1) {
        int u = __shfl_up_sync(0xFFFFFFFFu, s, o);
        if (lane >= o) s += u;
    }
    if (lane == 31) wsum[wid] = s;
    __syncthreads();
    if (t < 32) {
        int u = wsum[t];
        int ss = u;
#pragma unroll
        for (int o = 1; o < 32; o <<= 1) {
            int q = __shfl_up_sync(0xFFFFFFFFu, ss, o);
            if (t >= o) ss += q;
        }
        wsum[t] = ss - u;   // exclusive warp offset
    }
    __syncthreads();
    int excl = (s - v) + wsum[wid] + pbase;
    if (idx < N_NODES) { g_off[idx] = excl; g_cur[idx] = excl; }
    if (idx == N_NODES) g_off[N_NODES] = excl;

    // label-group scatter (warp-aggregated relative cursors)
    if (idx < N_NODES) {
        int lb = label[idx];
        if (lb < 1 || lb > 7) lb = 0;
        unsigned act = __activemask();
        unsigned peers = __match_any_sync(act, lb);
        int leader = __ffs(peers) - 1;
        int rank = __popc(peers & ((1u << lane) - 1u));
        int rel = 0;
        if (lane == leader) rel = atomicAdd(&g_lcur[lb], __popc(peers));
        rel = __shfl_sync(act, rel, leader);
        g_order[sbase[lb] + rel + rank] = idx;
    }
}

// CSR fill: 2 edges/thread + self loops
__global__ void k_fill(const int* __restrict__ ei) {
    int i = blockIdx.x * blockDim.x + threadIdx.x;
    int e2 = i * 2;
    if (e2 < N_EDGES) {
        int2 s2 = *(const int2*)(ei + e2);
        int2 d2 = *(const int2*)(ei + N_EDGES + e2);
        int p0 = atomicAdd(&g_cur[d2.x], 1);
        g_csr[p0] = s2.x;
        int p1 = atomicAdd(&g_cur[d2.y], 1);
        g_csr[p1] = s2.y;
    } else {
        int n = i - N_EDGES / 2;
        if (n >= 0 && n < N_NODES) {
            int pos = atomicAdd(&g_cur[n], 1);
            g_csr[pos] = n;
        }
    }
}

// tensor-core label-grouped GEMM (64 nodes x 128 out / block) with
// fragment-native epilogue: half2 direct store, quad-shuffle ai/aj dots.
__global__ void __launch_bounds__(128) k_ox(const float* __restrict__ x,
                                            const float* __restrict__ att) {
    int k = blockIdx.y;
    int gbase = g_base[k];
    int start = gbase + blockIdx.x * 64;
    int end   = gbase + g_counts[k];
    if (start >= end) return;
    int nEff = min(64, end - start);

    __shared__ __align__(16) __half xs[64 * XP];
    __shared__ __align__(16) __half ws[64 * XP];
    __shared__ float att_s[2 * DD];
    __shared__ int nid[64];
    __shared__ unsigned s_ajmax;

    int tid = threadIdx.x;
    int lane = tid & 31, wid = tid >> 5;
    if (tid < 64) nid[tid] = (tid < nEff) ? g_order[start + tid] : g_order[start];
    for (int t2 = tid; t2 < 2 * DD; t2 += 128) att_s[t2] = att[t2];
    if (tid == 0) s_ajmax = 0u;
    __syncthreads();

    {
        int j = tid >> 1, part = tid & 1;
        const float4* xr = (const float4*)x + (size_t)nid[j] * 32 + part * 16;
        __half2* dst = (__half2*)(xs + j * XP + part * 64);
#pragma unroll
        for (int i = 0; i < 16; i++) {
            float4 v = xr[i];
            dst[i * 2 + 0] = __floats2half2_rn(v.x, v.y);
            dst[i * 2 + 1] = __floats2half2_rn(v.z, v.w);
        }
    }

    float d[16][4];
#pragma unroll
    for (int nt = 0; nt < 16; nt++) { d[nt][0] = d[nt][1] = d[nt][2] = d[nt][3] = 0.f; }

    int wrow0 = wid * 16;

    if (k > 0) {
        const __half* Wg = g_Wh + (size_t)(k - 1) * DD * DD;
        for (int c = 0; c < 2; c++) {
            __syncthreads();
            {
                const int4* wsrc = (const int4*)(Wg + (size_t)c * 64 * DD);
                for (int idx = tid; idx < 1024; idx += 128) {
                    int dr = idx >> 4, i = idx & 15;
                    *(int4*)(ws + dr * XP + i * 8) = wsrc[dr * 16 + i];
                }
            }
            __syncthreads();
#pragma unroll
            for (int kt = 0; kt < 4; kt++) {
                int kb = kt * 16;
                unsigned a0, a1, a2, a3;
                {
                    int r  = (lane & 7) + ((lane >> 3) & 1) * 8;
                    int cc = (lane >> 4) * 8;
                    const __half* ap = xs + (wrow0 + r) * XP + (c * 64 + kb + cc);
                    unsigned sa = (unsigned)__cvta_generic_to_shared(ap);
                    asm volatile("ldmatrix.sync.aligned.m8n8.x4.shared.b16 {%0,%1,%2,%3}, [%4];"
                                 : "=r"(a0), "=r"(a1), "=r"(a2), "=r"(a3) : "r"(sa));
                }
#pragma unroll
                for (int np = 0; np < 8; np++) {
                    int n0 = np * 16;
                    unsigned b0, b1, b2, b3;
                    {
                        int kr = kb + (lane & 7) + ((lane >> 3) & 1) * 8;
                        int nc = n0 + (lane >> 4) * 8;
                        const __half* bp = ws + kr * XP + nc;
                        unsigned sb = (unsigned)__cvta_generic_to_shared(bp);
                        asm volatile("ldmatrix.sync.aligned.m8n8.x4.trans.shared.b16 {%0,%1,%2,%3}, [%4];"
                                     : "=r"(b0), "=r"(b1), "=r"(b2), "=r"(b3) : "r"(sb));
                    }
                    asm volatile("mma.sync.aligned.m16n8k16.row.col.f32.f16.f16.f32 "
                                 "{%0,%1,%2,%3}, {%4,%5,%6,%7}, {%8,%9}, {%0,%1,%2,%3};"
                                 : "+f"(d[np*2][0]), "+f"(d[np*2][1]), "+f"(d[np*2][2]), "+f"(d[np*2][3])
                                 : "r"(a0), "r"(a1), "r"(a2), "r"(a3), "r"(b0), "r"(b1));
                    asm volatile("mma.sync.aligned.m16n8k16.row.col.f32.f16.f16.f32 "
                                 "{%0,%1,%2,%3}, {%4,%5,%6,%7}, {%8,%9}, {%0,%1,%2,%3};"
                                 : "+f"(d[np*2+1][0]), "+f"(d[np*2+1][1]), "+f"(d[np*2+1][2]), "+f"(d[np*2+1][3])
                                 : "r"(a0), "r"(a1), "r"(a2), "r"(a3), "r"(b2), "r"(b3));
                }
            }
        }
    }

    // fragment-native epilogue
    int q  = lane & 3;
    int r0 = wrow0 + (lane >> 2);
    int r1 = r0 + 8;
    int j0ok = (r0 < nEff), j1ok = (r1 < nEff);
    int node0 = nid[r0], node1 = nid[r1];
    __half* oh0 = (__half*)g_oxh + (size_t)node0 * DD;
    __half* oh1 = (__half*)g_oxh + (size_t)node1 * DD;

    float si0 = 0.f, sj0 = 0.f, si1 = 0.f, sj1 = 0.f;
#pragma unroll
    for (int nt = 0; nt < 16; nt++) {
        int cc = nt * 8 + 2 * q;
        float av0 = att_s[cc], av1 = att_s[cc + 1];
        float bv0 = att_s[DD + cc], bv1 = att_s[DD + cc + 1];
        float2 x0 = __half22float2(*(const __half2*)(xs + r0 * XP + cc));
        float2 x1 = __half22float2(*(const __half2*)(xs + r1 * XP + cc));
        float v00 = x0.x + d[nt][0], v01 = x0.y + d[nt][1];
        float v10 = x1.x + d[nt][2], v11 = x1.y + d[nt][3];
        si0 += v00 * av0 + v01 * av1;
        sj0 += v00 * bv0 + v01 * bv1;
        si1 += v10 * av0 + v11 * av1;
        sj1 += v10 * bv0 + v11 * bv1;
        if (j0ok) *(__half2*)(oh0 + cc) = __floats2half2_rn(v00, v01);
        if (j1ok) *(__half2*)(oh1 + cc) = __floats2half2_rn(v10, v11);
    }
#pragma unroll
    for (int o = 1; o <= 2; o <<= 1) {
        si0 += __shfl_xor_sync(0xFFFFFFFFu, si0, o);
        sj0 += __shfl_xor_sync(0xFFFFFFFFu, sj0, o);
        si1 += __shfl_xor_sync(0xFFFFFFFFu, si1, o);
        sj1 += __shfl_xor_sync(0xFFFFFFFFu, sj1, o);
    }
    if (q == 0) {
        unsigned mx = 0u;
        if (j0ok) { g_ai[node0] = si0; g_aj[node0] = sj0; mx = fenc(sj0); }
        if (j1ok) { g_ai[node1] = si1; g_aj[node1] = sj1; unsigned m1 = fenc(sj1); if (m1 > mx) mx = m1; }
        if (mx) atomicMax(&s_ajmax, mx);
    }
    __syncthreads();
    if (tid == 0 && s_ajmax) atomicMax(&g_ajmax_u, s_ajmax);
}

// warp per dst node: single-pass softmax (global aj-max bound) + fp16 gather
__global__ void __launch_bounds__(256) k_agg(float* __restrict__ out) {
    int node = (blockIdx.x * blockDim.x + threadIdx.x) >> 5;
    int lane = threadIdx.x & 31;
    if (node >= N_NODES) return;
    int beg = g_off[node], end2 = g_off[node + 1];
    float ain = g_ai[node];
    float Mi = lrelu(ain + fdec(g_ajmax_u));

    float4 acc = make_float4(0.f, 0.f, 0.f, 0.f);
    float denom = 0.f;
    int e = beg;
    for (; e + 4 <= end2; e += 4) {
        int s0 = g_csr[e], s1 = g_csr[e + 1], s2 = g_csr[e + 2], s3 = g_csr[e + 3];
        float w0 = __expf(lrelu(ain + g_aj[s0]) - Mi);
        float w1 = __expf(lrelu(ain + g_aj[s1]) - Mi);
        float w2 = __expf(lrelu(ain + g_aj[s2]) - Mi);
        float w3 = __expf(lrelu(ain + g_aj[s3]) - Mi);
        uint2 p0 = g_oxh[s0 * 32 + lane];
        uint2 p1 = g_oxh[s1 * 32 + lane];
        uint2 p2 = g_oxh[s2 * 32 + lane];
        uint2 p3 = g_oxh[s3 * 32 + lane];
        denom += (w0 + w1) + (w2 + w3);
        float2 f01, f23;
        f01 = __half22float2(*reinterpret_cast<const __half2*>(&p0.x));
        f23 = __half22float2(*reinterpret_cast<const __half2*>(&p0.y));
        acc.x += w0 * f01.x; acc.y += w0 * f01.y; acc.z += w0 * f23.x; acc.w += w0 * f23.y;
        f01 = __half22float2(*reinterpret_cast<const __half2*>(&p1.x));
        f23 = __half22float2(*reinterpret_cast<const __half2*>(&p1.y));
        acc.x += w1 * f01.x; acc.y += w1 * f01.y; acc.z += w1 * f23.x; acc.w += w1 * f23.y;
        f01 = __half22float2(*reinterpret_cast<const __half2*>(&p2.x));
        f23 = __half22float2(*reinterpret_cast<const __half2*>(&p2.y));
        acc.x += w2 * f01.x; acc.y += w2 * f01.y; acc.z += w2 * f23.x; acc.w += w2 * f23.y;
        f01 = __half22float2(*reinterpret_cast<const __half2*>(&p3.x));
        f23 = __half22float2(*reinterpret_cast<const __half2*>(&p3.y));
        acc.x += w3 * f01.x; acc.y += w3 * f01.y; acc.z += w3 * f23.x; acc.w += w3 * f23.y;
    }
    for (; e < end2; e++) {
        int s = g_csr[e];
        float w = __expf(lrelu(ain + g_aj[s]) - Mi);
        uint2 p = g_oxh[s * 32 + lane];
        float2 f01 = __half22float2(*reinterpret_cast<const __half2*>(&p.x));
        float2 f23 = __half22float2(*reinterpret_cast<const __half2*>(&p.y));
        denom += w;
        acc.x += w * f01.x; acc.y += w * f01.y; acc.z += w * f23.x; acc.w += w * f23.y;
    }
    float inv = 1.f / (denom + 1e-16f);
    acc.x *= inv; acc.y *= inv; acc.z *= inv; acc.w *= inv;
    ((float4*)out)[node * 32 + lane] = acc;
}

// ---------------- launch ----------------
extern "C" void kernel_launch(void* const* d_in, const int* in_sizes, int n_in,
                              void* d_out, int out_size) {
    const float* x = nullptr;
    const int* ei = nullptr;
    const int* label = nullptr;
    const float* W = nullptr;
    const float* att = nullptr;
    for (int i = 0; i < n_in; i++) {
        switch (in_sizes[i]) {
            case N_NODES * DD:   x     = (const float*)d_in[i]; break;
            case 2 * N_EDGES:    ei    = (const int*)d_in[i];   break;
            case N_NODES:        label = (const int*)d_in[i];   break;
            case WSZ:            W     = (const float*)d_in[i]; break;
            case 2 * DD:         att   = (const float*)d_in[i]; break;
            default: break;
        }
    }
    float* out = (float*)d_out;

    k_init <<<(WSZ + 255) / 256, 256>>>(W);
    k_count<<<(N_EDGES / 2 + 255) / 256, 256>>>(ei, label);   // covers N (50000) too
    k_part <<<NB_SCAN, 1024>>>();
    k_off  <<<NB_SCAN, 1024>>>(label);
    k_fill <<<(N_EDGES / 2 + N_NODES + 255) / 256, 256>>>(ei);
    k_ox   <<<dim3((N_NODES + 63) / 64, NLAB), 128>>>(x, att);
    k_agg  <<<(N_NODES * 32 + 255) / 256, 256>>>(out);
}